// round 5
// baseline (speedup 1.0000x reference)
#include <cuda_runtime.h>
#include <cuda_fp16.h>
#include <cstdint>

// Problem constants (fixed by the dataset)
#define BB 4
#define NN 50000
#define RR 100000
#define EE 1600000
#define D1 32
#define D2 16
#define NEG 0.2f

// Bucket capacities (Poisson lambda=16 R-rows / 32 N-rows; overflow prob < 1e-25)
#define CAP_T1 128
#define CAP_X1 192
#define CAP_T2 128
#define CAP_P1 256

#define MW_R ((RR + 31) / 32)   // 3125 words
#define MW_N ((NN + 31) / 32)   // 1563 words

#define SCAN_T   (EE / 8)                  // 200000 scan threads (8 edges each)
#define SCAN_B   ((SCAN_T + 255) / 256)    // 782 scan blocks
#define H1_W     (NN * BB)                 // 200000 h1 row-warps total
#define H1B      512                       // h1 blocks appended to each scan kernel
#define H1_CHUNK (H1_W / 4)                // 50000 rows per scan kernel

// ---------------- device scratch (zero-init at module load; left zeroed per call) ----
__device__ __half g_h1[NN * BB * D1];  // 12.8 MB  [n][b][32] fp16
__device__ float g_T1[RR * BB * D1];   // 51.2 MB  [r][b][32]
__device__ float g_h2[NN * BB * D2];   // 12.8 MB  [n][b][16]
__device__ float g_T2[RR * BB * D2];   // 25.6 MB  [r][b][16]

__device__ int  g_cntT1[RR], g_cntX1[NN], g_cntT2[RR], g_cntP1[2];
__device__ int2 g_bT1[RR * CAP_T1];    // (col, val)
__device__ int2 g_bX1[NN * CAP_X1];    // (col, coef)
__device__ int2 g_bT2[RR * CAP_T2];    // (col, val)
__device__ int2 g_bP1[2 * CAP_P1];     // (col, coef)

__device__ unsigned g_mT1[MW_R], g_mT2[MW_R], g_mH2[MW_N];   // bit flags
__device__ int g_listX1[NN], g_listT2[RR];
__device__ int g_nX1, g_nT2;

// ---------------- h1 chunk: W1 column in regs, warp grid-strides rows ---------------
__device__ __forceinline__ void h1_chunk(int hb, int chunk, const float* __restrict__ x,
                                         const float* __restrict__ W1) {
    int lane = threadIdx.x & 31;
    float w0[D1];
#pragma unroll
    for (int k = 0; k < D1; k++) w0[k] = __ldg(&W1[k * D1 + lane]);
    int wid = hb * 8 + (threadIdx.x >> 5);
    int row0 = chunk * H1_CHUNK, rowEnd = row0 + H1_CHUNK;
    for (int w = row0 + wid; w < rowEnd; w += H1B * 8) {
        int n = w >> 2, b = w & 3;
        float xv = __ldg(&x[((size_t)b * NN + n) * D1 + lane]);
        float a0 = 0.f, a1 = 0.f;
#pragma unroll
        for (int k = 0; k < D1; k += 2) {
            a0 = fmaf(__shfl_sync(0xffffffffu, xv, k),     w0[k],     a0);
            a1 = fmaf(__shfl_sync(0xffffffffu, xv, k + 1), w0[k + 1], a1);
        }
        g_h1[(size_t)w * D1 + lane] = __float2half(a0 + a1);
    }
}

// ---------------- scan kernels (8 edges/thread, smem-cached masks) + h1 chunk -------
// S1: wi-edges into the 2 output nodes -> bP1 + mark mT2
__global__ void __launch_bounds__(256) k_s1(const int* __restrict__ wiRows,
        const int* __restrict__ wiCols, const float* __restrict__ wiVals,
        const float* __restrict__ diag2,
        const float* __restrict__ x, const float* __restrict__ W1) {
    if (blockIdx.x >= SCAN_B) { h1_chunk(blockIdx.x - SCAN_B, 0, x, W1); return; }
    int t = blockIdx.x * 256 + threadIdx.x;
    if (t >= SCAN_T) return;
    int base = t * 8;
    int4 a = __ldg((const int4*)(wiRows + base));
    int4 b4 = __ldg((const int4*)(wiRows + base + 4));
    int r[8] = {a.x, a.y, a.z, a.w, b4.x, b4.y, b4.z, b4.w};
#pragma unroll
    for (int j = 0; j < 8; j++) {
        if (r[j] >= NN - 2) {
            int s = r[j] - (NN - 2);
            int e = base + j;
            int col = __ldg(&wiCols[e]);
            float coef = __ldg(&wiVals[e]) * __ldg(&diag2[col]);
            int slot = atomicAdd(&g_cntP1[s], 1);
            if (slot < CAP_P1) g_bP1[s * CAP_P1 + slot] = make_int2(col, __float_as_int(coef));
            atomicOr(&g_mT2[col >> 5], 1u << (col & 31));
        }
    }
}

// S2: w-edges feeding mT2 rows -> bT2 + mark mH2 + listT2
__global__ void __launch_bounds__(256) k_s2(const int* __restrict__ wRows,
        const int* __restrict__ wCols, const float* __restrict__ wVals,
        const float* __restrict__ x, const float* __restrict__ W1) {
    __shared__ unsigned sm[MW_R];
    if (blockIdx.x >= SCAN_B) { h1_chunk(blockIdx.x - SCAN_B, 1, x, W1); return; }
    for (int i = threadIdx.x; i < MW_R; i += 256) sm[i] = g_mT2[i];
    __syncthreads();
    int t = blockIdx.x * 256 + threadIdx.x;
    if (t >= SCAN_T) return;
    int base = t * 8;
    int4 a = __ldg((const int4*)(wRows + base));
    int4 b4 = __ldg((const int4*)(wRows + base + 4));
    int r[8] = {a.x, a.y, a.z, a.w, b4.x, b4.y, b4.z, b4.w};
    unsigned m[8];
#pragma unroll
    for (int j = 0; j < 8; j++) m[j] = sm[r[j] >> 5];
#pragma unroll
    for (int j = 0; j < 8; j++) {
        if ((m[j] >> (r[j] & 31)) & 1u) {
            int e = base + j;
            int col = __ldg(&wCols[e]);
            int slot = atomicAdd(&g_cntT2[r[j]], 1);
            if (slot == 0) g_listT2[atomicAdd(&g_nT2, 1)] = r[j];
            if (slot < CAP_T2)
                g_bT2[r[j] * CAP_T2 + slot] = make_int2(col, __float_as_int(__ldg(&wVals[e])));
            atomicOr(&g_mH2[col >> 5], 1u << (col & 31));
        }
    }
}

// S3: wi-edges feeding mH2 nodes -> bX1 (coef = val*diag1) + mark mT1 + listX1
__global__ void __launch_bounds__(256) k_s3(const int* __restrict__ wiRows,
        const int* __restrict__ wiCols, const float* __restrict__ wiVals,
        const float* __restrict__ diag1,
        const float* __restrict__ x, const float* __restrict__ W1) {
    __shared__ unsigned sm[MW_N];
    if (blockIdx.x >= SCAN_B) { h1_chunk(blockIdx.x - SCAN_B, 2, x, W1); return; }
    for (int i = threadIdx.x; i < MW_N; i += 256) sm[i] = g_mH2[i];
    __syncthreads();
    int t = blockIdx.x * 256 + threadIdx.x;
    if (t >= SCAN_T) return;
    int base = t * 8;
    int4 a = __ldg((const int4*)(wiRows + base));
    int4 b4 = __ldg((const int4*)(wiRows + base + 4));
    int r[8] = {a.x, a.y, a.z, a.w, b4.x, b4.y, b4.z, b4.w};
    unsigned m[8];
#pragma unroll
    for (int j = 0; j < 8; j++) m[j] = sm[r[j] >> 5];
#pragma unroll
    for (int j = 0; j < 8; j++) {
        if ((m[j] >> (r[j] & 31)) & 1u) {
            int e = base + j;
            int col = __ldg(&wiCols[e]);
            float coef = __ldg(&wiVals[e]) * __ldg(&diag1[col]);
            int slot = atomicAdd(&g_cntX1[r[j]], 1);
            if (slot == 0) g_listX1[atomicAdd(&g_nX1, 1)] = r[j];
            if (slot < CAP_X1)
                g_bX1[r[j] * CAP_X1 + slot] = make_int2(col, __float_as_int(coef));
            atomicOr(&g_mT1[col >> 5], 1u << (col & 31));
        }
    }
}

// S4: w-edges feeding mT1 rows -> bT1 (28% hit rate: stream cols+vals unconditionally)
__global__ void __launch_bounds__(256) k_s4(const int* __restrict__ wRows,
        const int* __restrict__ wCols, const float* __restrict__ wVals,
        const float* __restrict__ x, const float* __restrict__ W1) {
    __shared__ unsigned sm[MW_R];
    if (blockIdx.x >= SCAN_B) { h1_chunk(blockIdx.x - SCAN_B, 3, x, W1); return; }
    for (int i = threadIdx.x; i < MW_R; i += 256) sm[i] = g_mT1[i];
    __syncthreads();
    int t = blockIdx.x * 256 + threadIdx.x;
    if (t >= SCAN_T) return;
    int base = t * 8;
    int4 a = __ldg((const int4*)(wRows + base));
    int4 b4 = __ldg((const int4*)(wRows + base + 4));
    int4 c0 = __ldg((const int4*)(wCols + base));
    int4 c1 = __ldg((const int4*)(wCols + base + 4));
    float4 v0 = __ldg((const float4*)(wVals + base));
    float4 v1 = __ldg((const float4*)(wVals + base + 4));
    int r[8] = {a.x, a.y, a.z, a.w, b4.x, b4.y, b4.z, b4.w};
    int cc[8] = {c0.x, c0.y, c0.z, c0.w, c1.x, c1.y, c1.z, c1.w};
    float vv[8] = {v0.x, v0.y, v0.z, v0.w, v1.x, v1.y, v1.z, v1.w};
    unsigned m[8];
#pragma unroll
    for (int j = 0; j < 8; j++) m[j] = sm[r[j] >> 5];
#pragma unroll
    for (int j = 0; j < 8; j++) {
        if ((m[j] >> (r[j] & 31)) & 1u) {
            int slot = atomicAdd(&g_cntT1[r[j]], 1);
            if (slot < CAP_T1)
                g_bT1[r[j] * CAP_T1 + slot] = make_int2(cc[j], __float_as_int(vv[j]));
        }
    }
}

// ---------------- T1[row] = sum_e v_e * h1[col_e]; one warp per row, full width ------
__global__ void __launch_bounds__(256) k_T1() {
    int w = (blockIdx.x * 256 + threadIdx.x) >> 5;
    if (w >= RR) return;
    int c = g_cntT1[w];
    if (c == 0) return;
    if (c > CAP_T1) c = CAP_T1;
    int lane = threadIdx.x & 31;
    int b = lane >> 3, q = lane & 7;
    const int2* bk = &g_bT1[w * CAP_T1];
    float4 acc = make_float4(0.f, 0.f, 0.f, 0.f);
    int k = 0;
    for (; k + 4 <= c; k += 4) {
        int2 e0 = __ldg(&bk[k]),     e1 = __ldg(&bk[k + 1]);
        int2 e2 = __ldg(&bk[k + 2]), e3 = __ldg(&bk[k + 3]);
        uint2 u0 = *(const uint2*)&g_h1[((size_t)e0.x * BB + b) * D1 + q * 4];
        uint2 u1 = *(const uint2*)&g_h1[((size_t)e1.x * BB + b) * D1 + q * 4];
        uint2 u2 = *(const uint2*)&g_h1[((size_t)e2.x * BB + b) * D1 + q * 4];
        uint2 u3 = *(const uint2*)&g_h1[((size_t)e3.x * BB + b) * D1 + q * 4];
        float v0 = __int_as_float(e0.y), v1 = __int_as_float(e1.y);
        float v2 = __int_as_float(e2.y), v3 = __int_as_float(e3.y);
        float2 a01, a23;
        a01 = __half22float2(*(__half2*)&u0.x); a23 = __half22float2(*(__half2*)&u0.y);
        acc.x = fmaf(v0, a01.x, acc.x); acc.y = fmaf(v0, a01.y, acc.y);
        acc.z = fmaf(v0, a23.x, acc.z); acc.w = fmaf(v0, a23.y, acc.w);
        a01 = __half22float2(*(__half2*)&u1.x); a23 = __half22float2(*(__half2*)&u1.y);
        acc.x = fmaf(v1, a01.x, acc.x); acc.y = fmaf(v1, a01.y, acc.y);
        acc.z = fmaf(v1, a23.x, acc.z); acc.w = fmaf(v1, a23.y, acc.w);
        a01 = __half22float2(*(__half2*)&u2.x); a23 = __half22float2(*(__half2*)&u2.y);
        acc.x = fmaf(v2, a01.x, acc.x); acc.y = fmaf(v2, a01.y, acc.y);
        acc.z = fmaf(v2, a23.x, acc.z); acc.w = fmaf(v2, a23.y, acc.w);
        a01 = __half22float2(*(__half2*)&u3.x); a23 = __half22float2(*(__half2*)&u3.y);
        acc.x = fmaf(v3, a01.x, acc.x); acc.y = fmaf(v3, a01.y, acc.y);
        acc.z = fmaf(v3, a23.x, acc.z); acc.w = fmaf(v3, a23.y, acc.w);
    }
    for (; k < c; k++) {
        int2 e0 = __ldg(&bk[k]);
        float v = __int_as_float(e0.y);
        uint2 u0 = *(const uint2*)&g_h1[((size_t)e0.x * BB + b) * D1 + q * 4];
        float2 a01 = __half22float2(*(__half2*)&u0.x);
        float2 a23 = __half22float2(*(__half2*)&u0.y);
        acc.x = fmaf(v, a01.x, acc.x); acc.y = fmaf(v, a01.y, acc.y);
        acc.z = fmaf(v, a23.x, acc.z); acc.w = fmaf(v, a23.y, acc.w);
    }
    *(float4*)&g_T1[((size_t)w * BB + b) * D1 + q * 4] = acc;
}

// ---------------- fused x1 + h2, one warp per active node (listX1, grid-stride) ------
__global__ void __launch_bounds__(256) k_x1h2(const float* __restrict__ W2) {
    __shared__ float sW[D1 * D2];
    __shared__ float sX[8][BB * D1];
    int t = threadIdx.x;
    for (int i = t; i < D1 * D2; i += 256) sW[i] = W2[i];
    __syncthreads();
    int lane = t & 31, wl = t >> 5;
    int gw = blockIdx.x * 8 + wl, nw = gridDim.x * 8;
    int b = lane >> 3, q = lane & 7;
    int nact = g_nX1;
    for (int i = gw; i < nact; i += nw) {
        int node = g_listX1[i];
        int c = g_cntX1[node]; if (c > CAP_X1) c = CAP_X1;
        const int2* bk = &g_bX1[node * CAP_X1];
        float4 acc = make_float4(0.f, 0.f, 0.f, 0.f);
        int k = 0;
        for (; k + 2 <= c; k += 2) {
            int2 e0 = __ldg(&bk[k]), e1 = __ldg(&bk[k + 1]);
            float4 t0 = *(const float4*)&g_T1[((size_t)e0.x * BB + b) * D1 + q * 4];
            float4 t1 = *(const float4*)&g_T1[((size_t)e1.x * BB + b) * D1 + q * 4];
            float v0 = __int_as_float(e0.y), v1 = __int_as_float(e1.y);
            acc.x = fmaf(v0, t0.x, acc.x); acc.y = fmaf(v0, t0.y, acc.y);
            acc.z = fmaf(v0, t0.z, acc.z); acc.w = fmaf(v0, t0.w, acc.w);
            acc.x = fmaf(v1, t1.x, acc.x); acc.y = fmaf(v1, t1.y, acc.y);
            acc.z = fmaf(v1, t1.z, acc.z); acc.w = fmaf(v1, t1.w, acc.w);
        }
        for (; k < c; k++) {
            int2 e0 = __ldg(&bk[k]);
            float v = __int_as_float(e0.y);
            float4 tv = *(const float4*)&g_T1[((size_t)e0.x * BB + b) * D1 + q * 4];
            acc.x = fmaf(v, tv.x, acc.x); acc.y = fmaf(v, tv.y, acc.y);
            acc.z = fmaf(v, tv.z, acc.z); acc.w = fmaf(v, tv.w, acc.w);
        }
        acc.x = acc.x > 0.f ? acc.x : NEG * acc.x;
        acc.y = acc.y > 0.f ? acc.y : NEG * acc.y;
        acc.z = acc.z > 0.f ? acc.z : NEG * acc.z;
        acc.w = acc.w > 0.f ? acc.w : NEG * acc.w;
        *(float4*)&sX[wl][b * D1 + q * 4] = acc;
        __syncwarp();
        int j = lane & 7;
        const float* xr = &sX[wl][b * D1];
        float a0 = 0.f, a1 = 0.f;
#pragma unroll
        for (int kk = 0; kk < D1; kk++) {
            float xv = xr[kk];
            a0 = fmaf(xv, sW[kk * D2 + j], a0);
            a1 = fmaf(xv, sW[kk * D2 + j + 8], a1);
        }
        g_h2[((size_t)node * BB + b) * D2 + j] = a0;
        g_h2[((size_t)node * BB + b) * D2 + j + 8] = a1;
        __syncwarp();
    }
}

// ---------------- T2[row] = sum_e v_e * h2[col_e]; one warp per active row (listT2) --
__global__ void __launch_bounds__(256) k_T2() {
    int lane = threadIdx.x & 31;
    int gw = blockIdx.x * 8 + (threadIdx.x >> 5), nw = gridDim.x * 8;
    int nact = g_nT2;
    int b = (lane >> 2) & 3, q = lane & 3;
    for (int i = gw; i < nact; i += nw) {
        int row = g_listT2[i];
        int c = g_cntT2[row]; if (c > CAP_T2) c = CAP_T2;
        if (lane >= 16) continue;
        const int2* bk = &g_bT2[row * CAP_T2];
        float4 acc = make_float4(0.f, 0.f, 0.f, 0.f);
        for (int k = 0; k < c; k++) {
            int2 e0 = __ldg(&bk[k]);
            float v = __int_as_float(e0.y);
            float4 h = *(const float4*)&g_h2[((size_t)e0.x * BB + b) * D2 + q * 4];
            acc.x = fmaf(v, h.x, acc.x); acc.y = fmaf(v, h.y, acc.y);
            acc.z = fmaf(v, h.z, acc.z); acc.w = fmaf(v, h.w, acc.w);
        }
        *(float4*)&g_T2[((size_t)row * BB + b) * D2 + q * 4] = acc;
    }
}

// ---------------- final heads + tail zeroing (state left clean for next call) --------
__global__ void __launch_bounds__(256) k_outz(const float* __restrict__ rw1,
        const float* __restrict__ rb1, const float* __restrict__ rw2,
        const float* __restrict__ rb2, float* __restrict__ out) {
    if (blockIdx.x == 0) {
        int warp = threadIdx.x >> 5;   // 8 warps: b = warp&3, s = warp>>2
        int lane = threadIdx.x & 31;
        int b = warp & 3, s = warp >> 2;
        int c = g_cntP1[s]; if (c > CAP_P1) c = CAP_P1;
        float acc = 0.f;
        for (int i = 0; i < c; i++) {
            int2 e = g_bP1[s * CAP_P1 + i];
            float coef = __int_as_float(e.y);
            if (lane < D2) acc = fmaf(coef, g_T2[((size_t)e.x * BB + b) * D2 + lane], acc);
        }
        float v = acc > 0.f ? acc : NEG * acc;
        const float* w = s ? rw2 : rw1;
        float y = (lane < D2) ? v * w[lane] : 0.f;
#pragma unroll
        for (int o = 16; o > 0; o >>= 1) y += __shfl_xor_sync(0xffffffffu, y, o);
        if (lane == 0) out[b * 2 + s] = y + (s ? rb2[0] : rb1[0]);
        __syncthreads();                       // all warps done reading g_cntP1
        if (threadIdx.x < 2) g_cntP1[threadIdx.x] = 0;
        if (threadIdx.x == 2) g_nX1 = 0;
        if (threadIdx.x == 3) g_nT2 = 0;
    } else {
        int i0 = (blockIdx.x - 1) * 256 + threadIdx.x;
        const int stride = 64 * 256;
        for (int i = i0; i < RR; i += stride) { g_cntT1[i] = 0; g_cntT2[i] = 0; }
        for (int i = i0; i < NN; i += stride) g_cntX1[i] = 0;
        for (int i = i0; i < MW_R; i += stride) { g_mT1[i] = 0u; g_mT2[i] = 0u; }
        for (int i = i0; i < MW_N; i += stride) g_mH2[i] = 0u;
    }
}

// ---------------- launch ----------------
extern "C" void kernel_launch(void* const* d_in, const int* in_sizes, int n_in,
                              void* d_out, int out_size) {
    const int*   wIdx   = (const int*)d_in[0];
    const float* wVal   = (const float*)d_in[1];
    const int*   wiIdx  = (const int*)d_in[2];
    const float* wiVal  = (const float*)d_in[3];
    const float* x      = (const float*)d_in[4];
    const float* W1     = (const float*)d_in[5];
    const float* diag1  = (const float*)d_in[6];
    const float* W2     = (const float*)d_in[7];
    const float* diag2  = (const float*)d_in[8];
    const float* rw1    = (const float*)d_in[9];
    const float* rb1    = (const float*)d_in[10];
    const float* rw2    = (const float*)d_in[11];
    const float* rb2    = (const float*)d_in[12];

    const int* wRows  = wIdx;
    const int* wCols  = wIdx + EE;
    const int* wiRows = wiIdx;
    const int* wiCols = wiIdx + EE;
    float* out = (float*)d_out;

    const int mixGrid = SCAN_B + H1B;   // 782 + 512

    k_s1<<<mixGrid, 256>>>(wiRows, wiCols, wiVal, diag2, x, W1);
    k_s2<<<mixGrid, 256>>>(wRows, wCols, wVal, x, W1);
    k_s3<<<mixGrid, 256>>>(wiRows, wiCols, wiVal, diag1, x, W1);
    k_s4<<<mixGrid, 256>>>(wRows, wCols, wVal, x, W1);
    k_T1<<<(RR * 32 + 255) / 256, 256>>>();
    k_x1h2<<<64, 256>>>(W2);
    k_T2<<<8, 256>>>();
    k_outz<<<65, 256>>>(rw1, rb1, rw2, rb2, out);
}